// round 1
// baseline (speedup 1.0000x reference)
#include <cuda_runtime.h>
#include <cfloat>

// Problem constants: V is [N, M] fp32; out is [N, M] fp32.
#define Mm    8192
#define Nn    1024
#define STEPS 8192   // num_rounds(8) * N
#define G     64     // CTAs in the persistent kernel (columns split across CTAs)
#define T     128    // threads per CTA -> 1 column per thread (G*T == Mm)

// Static scratch (no allocation allowed). Re-initialized every launch by init_kernel.
__device__ __align__(16) float g_partials[STEPS * G]; // per-step per-CTA exp-sum; 0 == "not ready" (true partials are >= T >= 128)
__device__ float g_rmin[Nn];                           // per-row min of V

// ---------------------------------------------------------------------------
// init: zero the partials (sentinel) and compute row mins of V.
// grid = 1024 blocks x 256 threads. 1024*256 threads * 1 float2 = 2MB zeroed exactly.
// ---------------------------------------------------------------------------
__global__ void softrr_init(const float* __restrict__ V) {
    const int b = blockIdx.x, t = threadIdx.x;

    // zero partials: 524288 floats = 262144 float2, exactly 1024*256 threads
    const int id = b * 256 + t;
    reinterpret_cast<float2*>(g_partials)[id] = make_float2(0.0f, 0.0f);

    // row min for row b
    const float* row = V + (size_t)b * Mm;
    float mn = FLT_MAX;
    for (int j = t; j < Mm; j += 256) mn = fminf(mn, row[j]);
    #pragma unroll
    for (int o = 16; o; o >>= 1) mn = fminf(mn, __shfl_down_sync(0xffffffffu, mn, o));
    __shared__ float s[8];
    if ((t & 31) == 0) s[t >> 5] = mn;
    __syncthreads();
    if (t == 0) {
        float r = s[0];
        #pragma unroll
        for (int w = 1; w < 8; w++) r = fminf(r, s[w]);
        g_rmin[b] = r;
    }
}

// ---------------------------------------------------------------------------
// main persistent kernel: 64 CTAs, 128 threads each, one column per thread.
// Per step: e = exp((v - rmin + 1)*c); S = global sum(e); y = e/S;
//           out[row] += y; c *= (1 - y).
// Cross-CTA sync: data-is-the-flag. Each CTA stores its positive partial into
// a step-indexed slot (zero-initialized); warp 0 of every CTA polls all 64
// slots until nonzero, then reduces them in a FIXED order (deterministic).
// ---------------------------------------------------------------------------
__global__ void __launch_bounds__(T, 1) softrr_main(const float* __restrict__ V,
                                                    float* __restrict__ out) {
    const int g    = blockIdx.x;
    const int t    = threadIdx.x;
    const int lane = t & 31;
    const int wid  = t >> 5;
    const int col  = g * T + t;

    __shared__ float s_rmin[Nn];
    __shared__ float s_warp[4];
    __shared__ float s_S;

    for (int i = t; i < Nn; i += T) s_rmin[i] = g_rmin[i];
    __syncthreads();

    float c = 1.0f;
    float v_next = V[col];      // row 0 prefetch
    float o_next = 0.0f;        // round 0: overwrite (out is poisoned)

    for (int r = 0; r < STEPS; r++) {
        const int row = r & (Nn - 1);

        const float a = (v_next - s_rmin[row]) + 1.0f;
        const float e = __expf(a * c);   // z in [0, ~10]: no max-subtraction needed
        const float oacc = o_next;

        // prefetch next step's V element and out accumulator (independent of S)
        if (r + 1 < STEPS) {
            const int rn = (r + 1) & (Nn - 1);
            v_next = V[rn * Mm + col];
            o_next = (r + 1 >= Nn) ? out[rn * Mm + col] : 0.0f;
        }

        // intra-CTA reduction of e (fixed tree -> deterministic)
        float p = e;
        #pragma unroll
        for (int o = 16; o; o >>= 1) p += __shfl_down_sync(0xffffffffu, p, o);
        if (lane == 0) s_warp[wid] = p;
        __syncthreads();

        if (wid == 0) {
            if (lane == 0) {
                const float P = (s_warp[0] + s_warp[1]) + (s_warp[2] + s_warp[3]);
                // publish partial (P >= 128 > 0, so nonzero == ready)
                asm volatile("st.global.cg.f32 [%0], %1;"
                             :: "l"(g_partials + (size_t)r * G + g), "f"(P) : "memory");
            }
            // warp 0 polls all 64 slots (2 per lane), L1-bypassing volatile loads
            volatile float* vp = g_partials + (size_t)r * G;
            float p0, p1;
            do {
                p0 = vp[2 * lane];
                p1 = vp[2 * lane + 1];
            } while (__ballot_sync(0xffffffffu, (p0 != 0.0f) && (p1 != 0.0f)) != 0xffffffffu);

            // fixed-order reduction of the 64 partials (identical on every CTA)
            float s2 = p0 + p1;
            #pragma unroll
            for (int o = 16; o; o >>= 1) s2 += __shfl_down_sync(0xffffffffu, s2, o);
            if (lane == 0) s_S = s2;
        }
        __syncthreads();

        const float S = s_S;
        const float y = __fdividef(e, S);
        out[row * Mm + col] = oacc + y;       // round 0: oacc==0 -> plain store
        c = __fmaf_rn(-y, c, c);              // c *= (1 - y)
    }
}

extern "C" void kernel_launch(void* const* d_in, const int* in_sizes, int n_in,
                              void* d_out, int out_size) {
    const float* V = (const float*)d_in[0];
    float* out = (float*)d_out;
    (void)in_sizes; (void)n_in; (void)out_size;

    softrr_init<<<Nn, 256>>>(V);
    softrr_main<<<G, T>>>(V, out);
}

// round 2
// speedup vs baseline: 5.9612x; 5.9612x over previous
#include <cuda_runtime.h>
#include <cfloat>
#include <cstdint>

// Problem: V [1024, 8192] fp32 -> out [1024, 8192] fp32
#define Mm    8192
#define Nn    1024
#define STEPS 8192   // 8 rounds * 1024 rows
#define C     8      // cluster size (CTAs) — one cluster covers all columns
#define TPB   1024   // threads per CTA -> exactly 1 column per thread
#define D     2      // slot ring depth (phases)

__device__ float g_rmin[Nn];   // per-row min of V (precomputed each launch)

// ---------------------------------------------------------------------------
// init: per-row min of V. grid = 1024 blocks x 256 threads.
// ---------------------------------------------------------------------------
__global__ void softrr_init(const float* __restrict__ V) {
    const int b = blockIdx.x, t = threadIdx.x;
    const float* row = V + (size_t)b * Mm;
    float mn = FLT_MAX;
    for (int j = t; j < Mm; j += 256) mn = fminf(mn, row[j]);
    #pragma unroll
    for (int o = 16; o; o >>= 1) mn = fminf(mn, __shfl_down_sync(0xffffffffu, mn, o));
    __shared__ float s[8];
    if ((t & 31) == 0) s[t >> 5] = mn;
    __syncthreads();
    if (t == 0) {
        float r = s[0];
        #pragma unroll
        for (int w = 1; w < 8; w++) r = fminf(r, s[w]);
        g_rmin[b] = r;
    }
}

// ---------------------------------------------------------------------------
// main: ONE cluster of 8 CTAs x 1024 threads (8192 threads = 8192 columns).
// Per step: e = exp((v - rmin + 1)*c); S = global sum(e); y = e/S;
//           out[row] (+)= y; c *= (1 - y).
// Cross-CTA sum via DSMEM: each CTA pushes its partial into a step-phased
// slot in EVERY cluster CTA's smem (data-is-the-flag: partial >= 1024 > 0);
// all warps poll their own LOCAL smem slots (no L2 traffic), then reduce the
// 8 partials in a fixed order (deterministic, identical S everywhere).
// ---------------------------------------------------------------------------
__global__ void __launch_bounds__(TPB, 1) __cluster_dims__(C, 1, 1)
softrr_main(const float* __restrict__ V, float* __restrict__ out) {
    __shared__ float s_rmin[Nn];
    __shared__ float s_wp[32];                        // per-warp partials
    __shared__ __align__(16) float s_slot[D * C];     // DSMEM-written ring slots

    const int tid  = threadIdx.x;
    const int lane = tid & 31;
    const int wid  = tid >> 5;
    const int rank = blockIdx.x;           // single cluster: ctarank == blockIdx.x
    const int col  = rank * TPB + tid;

    volatile float* vslot = s_slot;
    uint32_t slot_base = (uint32_t)__cvta_generic_to_shared(s_slot);

    if (tid < D * C) s_slot[tid] = 0.0f;
    s_rmin[tid] = g_rmin[tid];
    __syncthreads();
    // all CTAs' slots must be zero before anyone publishes step 0
    asm volatile("barrier.cluster.arrive.aligned;" ::: "memory");
    asm volatile("barrier.cluster.wait.aligned;"   ::: "memory");

    float c      = 1.0f;
    float v_next = V[col];   // row 0 prefetch
    float o_next = 0.0f;     // round 0 overwrites (out is poisoned)

    for (int r = 0; r < STEPS; r++) {
        const int row = r & (Nn - 1);

        const float a    = (v_next - s_rmin[row]) + 1.0f;
        const float e    = __expf(a * c);      // z in [0,~11]: no max-subtract needed
        const float oacc = o_next;

        // prefetch next step's V / out element (independent of S; hides L2 latency)
        if (r + 1 < STEPS) {
            const int rn = (r + 1) & (Nn - 1);
            v_next = V[(size_t)rn * Mm + col];
            o_next = (r + 1 >= Nn) ? out[(size_t)rn * Mm + col] : 0.0f;
        }

        // intra-warp reduce (fixed tree)
        float p = e;
        #pragma unroll
        for (int o = 16; o; o >>= 1) p += __shfl_down_sync(0xffffffffu, p, o);
        if (lane == 0) s_wp[wid] = p;
        __syncthreads();   // also fences the slot ring: all warps are past step r-1's poll

        const int ph = r & (D - 1);
        if (wid == 0) {
            // combine 32 warp partials (fixed tree)
            float q = s_wp[lane];
            #pragma unroll
            for (int o = 16; o; o >>= 1) q += __shfl_down_sync(0xffffffffu, q, o);
            const float P = __shfl_sync(0xffffffffu, q, 0);

            // publish P into slot[ph][rank] of every cluster CTA (incl. self)
            if (lane < C) {
                uint32_t la = slot_base + (uint32_t)(ph * C + rank) * 4u;
                uint32_t ra;
                asm volatile("mapa.shared::cluster.u32 %0, %1, %2;"
                             : "=r"(ra) : "r"(la), "r"(lane));
                asm volatile("st.shared::cluster.f32 [%0], %1;"
                             :: "r"(ra), "f"(P) : "memory");
            }
            // recycle the previous phase's slots (safe: reuse is >=2 DSMEM hops away)
            if (lane == 0 && r > 0) {
                const int pph = (r - 1) & (D - 1);
                *reinterpret_cast<float4*>(&s_slot[pph * C])     = make_float4(0, 0, 0, 0);
                *reinterpret_cast<float4*>(&s_slot[pph * C + 4]) = make_float4(0, 0, 0, 0);
            }
        }

        // ALL warps poll local smem slots until all C partials have landed
        float pv;
        do {
            pv = (lane < C) ? vslot[ph * C + lane] : 1.0f;
        } while (__ballot_sync(0xffffffffu, pv != 0.0f) != 0xffffffffu);
        if (lane >= C) pv = 0.0f;

        // fixed-order reduce of the C partials (same everywhere)
        float S = pv;
        #pragma unroll
        for (int o = 4; o; o >>= 1) S += __shfl_down_sync(0xffffffffu, S, o);
        S = __shfl_sync(0xffffffffu, S, 0);

        const float y = __fdividef(e, S);
        out[(size_t)row * Mm + col] = oacc + y;  // round 0: oacc==0 -> plain store
        c = __fmaf_rn(-y, c, c);                 // c *= (1 - y)
    }
}

extern "C" void kernel_launch(void* const* d_in, const int* in_sizes, int n_in,
                              void* d_out, int out_size) {
    const float* V = (const float*)d_in[0];
    float* out = (float*)d_out;
    (void)in_sizes; (void)n_in; (void)out_size;

    softrr_init<<<Nn, 256>>>(V);
    softrr_main<<<C, TPB>>>(V, out);
}